// round 14
// baseline (speedup 1.0000x reference)
#include <cuda_runtime.h>
#include <cuda_bf16.h>

typedef unsigned long long ull;

#define NCTAS 147
#define NT    512
#define ROWS  28          // rows per CTA (last CTA partially valid)
#define HPAIR 7           // row pairs per thread (half of 14 rows)
#define RS    32          // padded row stride (floats); halves 16B-aligned
#define HH    256
#define EE    64
#define VV    64
#define ZZ    128
#define TS    119
#define BTOT  4096

// Weight layouts (built by prep), 20B per (k,j):
// g_wrz4[k][j] = (w_r, w_r, w_z, w_z)  -> one LDG.128, FFMA2-ready, no MOVs
// g_wn1 [k][j] = w_n                    -> 4B + one dup2
// k-slot bases: L0 wi:0(K=64) wh:64 | L1 wi:320 wh:576 | L2 wi:832 wh:1088
__device__ float4 g_wrz4[1344 * 256];
__device__ float  g_wn1 [1344 * 256];
__device__ float4 g_z3  [128 * 256];      // z2h: (row j, 256+j, 512+j, 0)
__device__ float2 g_ow  [256 * 64];       // out_w transposed + duplicated: [k][v]

struct SM {
    float hb[2][3][HH][RS];     // hidden state, double-buffered   196,608 B
    float xz[ZZ][RS];           // z/embedding; lbuf aliases this   16,384 B
    float br[3][HH];            // b_ih_r + b_hh_r
    float bz[3][HH];            // b_ih_z + b_hh_z
    float bin_[3][HH];          // b_ih_n
    float bhn_[3][HH];          // b_hh_n                           12,288 B
    int   tok[ROWS];            //                                     112 B
};                              // total ~225,392 B < 227 KB limit

__device__ __forceinline__ int slotof(int r) { return r + (r >= 14 ? 2 : 0); }

// ---------------- packed f32x2 helpers ----------------
__device__ __forceinline__ ull dup2(float v) {
    ull r; asm("mov.b64 %0, {%1, %1};" : "=l"(r) : "f"(v)); return r;
}
__device__ __forceinline__ void fma2(ull& d, ull a, ull b) {
    asm("fma.rn.f32x2 %0, %1, %2, %0;" : "+l"(d) : "l"(a), "l"(b));
}
__device__ __forceinline__ float f2lo(ull v) { return __uint_as_float((unsigned)(v & 0xffffffffULL)); }
__device__ __forceinline__ float f2hi(ull v) { return __uint_as_float((unsigned)(v >> 32)); }

// ---------------- flag-proof ~1ulp activations ----------------
__device__ __forceinline__ float exp_acc(float x) {
    x = fminf(fmaxf(x, -87.0f), 87.0f);
    float n = rintf(x * 1.4426950408889634f);
    float r = fmaf(n, -6.93145752e-01f, x);
    r = fmaf(n, -1.42860677e-06f, r);
    float p = 1.98412698412e-4f;
    p = fmaf(p, r, 1.38888888889e-3f);
    p = fmaf(p, r, 8.33333333333e-3f);
    p = fmaf(p, r, 4.16666666667e-2f);
    p = fmaf(p, r, 1.66666666667e-1f);
    p = fmaf(p, r, 0.5f);
    p = fmaf(p, r, 1.0f);
    p = fmaf(p, r, 1.0f);
    float sc = __int_as_float(((int)n + 127) << 23);
    return p * sc;
}
__device__ __forceinline__ float sigm(float x) {
    float e = exp_acc(-x);
    return __fdiv_rn(1.0f, 1.0f + e);
}
__device__ __forceinline__ float mytanh(float x) {
    float a = fabsf(x);
    float e = exp_acc(-2.0f * a);
    float r = __fdiv_rn(1.0f - e, 1.0f + e);
    return copysignf(r, x);
}

// ---------------- prep kernel ----------------
__global__ void prep_kernel(
    const float* __restrict__ wi0, const float* __restrict__ wh0,
    const float* __restrict__ wi1, const float* __restrict__ wh1,
    const float* __restrict__ wi2, const float* __restrict__ wh2,
    const float* __restrict__ z2h_w, const float* __restrict__ out_w)
{
    int bx = blockIdx.x;
    int j = threadIdx.x;
    if (bx < 1344) {
        const float* W; int ld, kk;
        if      (bx <   64) { W = wi0; ld =  64; kk = bx;        }
        else if (bx <  320) { W = wh0; ld = 256; kk = bx -   64; }
        else if (bx <  576) { W = wi1; ld = 256; kk = bx -  320; }
        else if (bx <  832) { W = wh1; ld = 256; kk = bx -  576; }
        else if (bx < 1088) { W = wi2; ld = 256; kk = bx -  832; }
        else                { W = wh2; ld = 256; kk = bx - 1088; }
        float wr = W[(size_t)j * ld + kk];
        float wz = W[(size_t)(256 + j) * ld + kk];
        float wn = W[(size_t)(512 + j) * ld + kk];
        g_wrz4[bx * 256 + j] = make_float4(wr, wr, wz, wz);
        g_wn1 [bx * 256 + j] = wn;
    } else if (bx < 1472) {
        int kz = bx - 1344;
        float4 v;
        v.x = z2h_w[(size_t)j * ZZ + kz];
        v.y = z2h_w[(size_t)(256 + j) * ZZ + kz];
        v.z = z2h_w[(size_t)(512 + j) * ZZ + kz];
        v.w = 0.0f;
        g_z3[kz * 256 + j] = v;
    } else {
        int m = bx - 1472;                 // 0..63
        int id = m * 256 + j;
        int k = id >> 6, v = id & 63;
        float w = out_w[(size_t)v * HH + k];
        g_ow[k * 64 + v] = make_float2(w, w);
    }
}

// ---------------- GEMM phase: thread owns gate j, 3 gates, 7 row-pairs ----------------
// Hybrid-dup weights: (wr,wr,wz,wz) one LDG.128 -> no MOVs; wn 4B + 1 dup2.
// acc sections: (0,1,SN) <- (r, z, n)
template<int K, int SN>
__device__ __forceinline__ void gemm3(const ulonglong2* __restrict__ wrz4,
                                      const float* __restrict__ wn,
                                      const float* __restrict__ xb,
                                      ull (&acc)[4][HPAIR], int j)
{
    const ulonglong2* wp = wrz4 + j;
    const float*      np = wn  + j;
#pragma unroll 4
    for (int k = 0; k < K; k++) {
        ulonglong2 w = __ldg(wp + (size_t)k * 256);
        float     nv = __ldg(np + (size_t)k * 256);
        ull wr = w.x, wz = w.y, wnn = dup2(nv);
        const ulonglong2* xq = (const ulonglong2*)(xb + (size_t)k * RS);
        ulonglong2 x0 = xq[0], x1 = xq[1], x2 = xq[2];
        ull x6 = ((const ull*)(xq + 3))[0];
        fma2(acc[0][0], wr, x0.x); fma2(acc[0][1], wr, x0.y);
        fma2(acc[0][2], wr, x1.x); fma2(acc[0][3], wr, x1.y);
        fma2(acc[0][4], wr, x2.x); fma2(acc[0][5], wr, x2.y);
        fma2(acc[0][6], wr, x6);
        fma2(acc[1][0], wz, x0.x); fma2(acc[1][1], wz, x0.y);
        fma2(acc[1][2], wz, x1.x); fma2(acc[1][3], wz, x1.y);
        fma2(acc[1][4], wz, x2.x); fma2(acc[1][5], wz, x2.y);
        fma2(acc[1][6], wz, x6);
        fma2(acc[SN][0], wnn, x0.x); fma2(acc[SN][1], wnn, x0.y);
        fma2(acc[SN][2], wnn, x1.x); fma2(acc[SN][3], wnn, x1.y);
        fma2(acc[SN][4], wnn, x2.x); fma2(acc[SN][5], wnn, x2.y);
        fma2(acc[SN][6], wnn, x6);
    }
}

// One GRU layer step (double-buffered: read cb, write nb; NO internal barriers).
template<int KIN>
__device__ __forceinline__ void layer_step(SM* s, const float* __restrict__ xb,
                                           const ulonglong2* __restrict__ wrzI,
                                           const float* __restrict__ wnI,
                                           const ulonglong2* __restrict__ wrzH,
                                           const float* __restrict__ wnH,
                                           const float* __restrict__ hcur,      // &hb[cb][l][0][ro]
                                           const float* __restrict__ hcur_row,  // &hb[cb][l][j][ro]
                                           float* __restrict__ hnxt_row,        // &hb[nb][l][j][ro]
                                           int l, int j)
{
    ull acc[4][HPAIR];
    {
        ull b0 = dup2(s->br[l][j]);
        ull b1 = dup2(s->bz[l][j]);
        ull b2 = dup2(s->bin_[l][j]);
        ull b3 = dup2(s->bhn_[l][j]);
#pragma unroll
        for (int p = 0; p < HPAIR; p++) {
            acc[0][p] = b0; acc[1][p] = b1; acc[2][p] = b2; acc[3][p] = b3;
        }
    }
    gemm3<KIN, 2>(wrzI, wnI, xb,   acc, j);   // x @ wi^T -> r, z, inn
    gemm3<HH,  3>(wrzH, wnH, hcur, acc, j);   // h @ wh^T -> r, z, hn
    // no barrier: writes go to the other buffer
#pragma unroll
    for (int p = 0; p < HPAIR; p++) {
        float2 hold = *(const float2*)(hcur_row + 2 * p);
        float rlo = sigm(f2lo(acc[0][p])), rhi = sigm(f2hi(acc[0][p]));
        float ulo = sigm(f2lo(acc[1][p])), uhi = sigm(f2hi(acc[1][p]));
        float nlo = mytanh(f2lo(acc[2][p]) + rlo * f2lo(acc[3][p]));
        float nhi = mytanh(f2hi(acc[2][p]) + rhi * f2hi(acc[3][p]));
        float2 hnew;
        hnew.x = (1.0f - ulo) * nlo + ulo * hold.x;
        hnew.y = (1.0f - uhi) * nhi + uhi * hold.y;
        *(float2*)(hnxt_row + 2 * p) = hnew;
    }
}

__global__ void __launch_bounds__(NT, 1) moldec_kernel(
    const float* __restrict__ z,     const float* __restrict__ emb,
    const float* __restrict__ z2h_b, const float* __restrict__ out_b,
    const float* __restrict__ bi0, const float* __restrict__ bh0,
    const float* __restrict__ bi1, const float* __restrict__ bh1,
    const float* __restrict__ bi2, const float* __restrict__ bh2,
    float* __restrict__ out)
{
    extern __shared__ char smraw[];
    SM* s = (SM*)smraw;
    const int tid = threadIdx.x;
    const int row0 = blockIdx.x * ROWS;
    const int j  = tid & 255;      // gate index
    const int rh = tid >> 8;       // row half
    const int ro = rh * 16;        // slot offset of this half
    float* lbuf = &s->xz[0][0];    // aliases xz (time-disjoint; stride VV+1)

    // combined biases to smem
    {
        const float* bip[3] = {bi0, bi1, bi2};
        const float* bhp[3] = {bh0, bh1, bh2};
        for (int i = tid; i < 3 * HH; i += NT) {
            int l = i >> 8, jj = i & 255;
            s->br[l][jj]   = bip[l][jj]          + bhp[l][jj];
            s->bz[l][jj]   = bip[l][HH + jj]     + bhp[l][HH + jj];
            s->bin_[l][jj] = bip[l][2 * HH + jj];
            s->bhn_[l][jj] = bhp[l][2 * HH + jj];
        }
    }
    // stage z transposed (k-major, slot-mapped), zero-fill invalid rows
    for (int i = tid; i < ZZ * ROWS; i += NT) {
        int r = i >> 7, k = i & 127;
        int grow = row0 + r;
        s->xz[k][slotof(r)] = (grow < BTOT) ? z[(size_t)grow * ZZ + k] : 0.0f;
    }
    // zero pad slots (14,15,30,31) of every k-row in BOTH hb buffers + xz
    for (int i = tid; i < 2 * 3 * HH + ZZ; i += NT) {
        float* rowp;
        if (i < 2 * 3 * HH) {
            int b = i / (3 * HH), rem = i - b * 3 * HH;
            rowp = &s->hb[b][rem >> 8][rem & 255][0];
        } else {
            rowp = &s->xz[i - 2 * 3 * HH][0];
        }
        rowp[14] = 0.0f; rowp[15] = 0.0f; rowp[30] = 0.0f; rowp[31] = 0.0f;
    }
    if (tid < ROWS) s->tok[tid] = 1;
    __syncthreads();

    // initial hidden into buffer 0: h0[l] = tanh(z @ z2h_w^T + z2h_b)
    {
        ull acc[4][HPAIR];
#pragma unroll
        for (int ss = 0; ss < 3; ss++) {
            ull b = dup2(z2h_b[ss * 256 + j]);
#pragma unroll
            for (int p = 0; p < HPAIR; p++) acc[ss][p] = b;
        }
#pragma unroll
        for (int p = 0; p < HPAIR; p++) acc[3][p] = 0ULL;
        const float4* zp = g_z3 + j;
#pragma unroll 2
        for (int k = 0; k < ZZ; k++) {
            float4 wc = __ldg(zp + (size_t)k * 256);
            ull wa = dup2(wc.x), wb = dup2(wc.y), wcn = dup2(wc.z);
            const ull* xq = (const ull*)(&s->xz[k][ro]);
#pragma unroll
            for (int p = 0; p < HPAIR; p++) {
                ull xv = xq[p];
                fma2(acc[0][p], wa, xv);
                fma2(acc[1][p], wb, xv);
                fma2(acc[2][p], wcn, xv);
            }
        }
#pragma unroll
        for (int ss = 0; ss < 3; ss++) {
            float* hrow = &s->hb[0][ss][j][ro];
#pragma unroll
            for (int p = 0; p < HPAIR; p++) {
                float2 hv;
                hv.x = mytanh(f2lo(acc[ss][p]));
                hv.y = mytanh(f2hi(acc[ss][p]));
                *(float2*)(hrow + 2 * p) = hv;
            }
        }
        __syncthreads();
    }

    const ulonglong2* wrzi0 = (const ulonglong2*)g_wrz4;
    const ulonglong2* wrzh0 = (const ulonglong2*)(g_wrz4 +   64 * 256);
    const ulonglong2* wrzi1 = (const ulonglong2*)(g_wrz4 +  320 * 256);
    const ulonglong2* wrzh1 = (const ulonglong2*)(g_wrz4 +  576 * 256);
    const ulonglong2* wrzi2 = (const ulonglong2*)(g_wrz4 +  832 * 256);
    const ulonglong2* wrzh2 = (const ulonglong2*)(g_wrz4 + 1088 * 256);
    const float* wni0 = g_wn1;              const float* wnh0 = g_wn1 +   64 * 256;
    const float* wni1 = g_wn1 +  320 * 256; const float* wnh1 = g_wn1 +  576 * 256;
    const float* wni2 = g_wn1 +  832 * 256; const float* wnh2 = g_wn1 + 1088 * 256;

    // out-proj thread mapping
    const int v = tid & 63;
    const int g = tid >> 6;            // 0..7
    const int gval = (g < 7);
    const int so0 = gval ? slotof(g * 4)     : 0;
    const int so1 = gval ? slotof(g * 4 + 2) : 0;
    const float ob = out_b[v];

    // decode loop
    for (int t = 0; t < TS; t++) {
        const int cb = t & 1, nb = cb ^ 1;

        // embedding gather into xz (k-major, slot-mapped)
        for (int i = tid; i < EE * ROWS; i += NT) {
            int r = i >> 6, k = i & 63;
            s->xz[k][slotof(r)] = emb[(size_t)s->tok[r] * EE + k];
        }
        __syncthreads();                                        // B1

        layer_step<EE>(s, &s->xz[0][ro], wrzi0, wni0, wrzh0, wnh0,
                       &s->hb[cb][0][0][ro], &s->hb[cb][0][j][ro], &s->hb[nb][0][j][ro], 0, j);
        __syncthreads();                                        // B2
        layer_step<HH>(s, &s->hb[nb][0][0][ro], wrzi1, wni1, wrzh1, wnh1,
                       &s->hb[cb][1][0][ro], &s->hb[cb][1][j][ro], &s->hb[nb][1][j][ro], 1, j);
        __syncthreads();                                        // B3
        layer_step<HH>(s, &s->hb[nb][1][0][ro], wrzi2, wni2, wrzh2, wnh2,
                       &s->hb[cb][2][0][ro], &s->hb[cb][2][j][ro], &s->hb[nb][2][j][ro], 2, j);
        __syncthreads();                                        // B4

        // output projection: logits = hb[nb][2] @ out_w^T + out_b
        {
            ull o0 = dup2(ob);
            ull o1 = o0;
            const float* xs = &s->hb[nb][2][0][0];
            const ull* owp = (const ull*)g_ow;
            for (int kb = 0; kb < HH; kb += 8) {
                ull wreg[8];
#pragma unroll
                for (int i = 0; i < 8; i++) wreg[i] = owp[(kb + i) * 64 + v];
#pragma unroll
                for (int i = 0; i < 8; i++) {
                    const float* xrow = xs + (size_t)(kb + i) * RS;
                    fma2(o0, wreg[i], *(const ull*)(xrow + so0));
                    fma2(o1, wreg[i], *(const ull*)(xrow + so1));
                }
            }
            if (gval) {
                int r0 = g * 4;
                float l0 = f2lo(o0), l1 = f2hi(o0), l2 = f2lo(o1), l3 = f2hi(o1);
                lbuf[(r0 + 0) * (VV + 1) + v] = l0;
                lbuf[(r0 + 1) * (VV + 1) + v] = l1;
                lbuf[(r0 + 2) * (VV + 1) + v] = l2;
                lbuf[(r0 + 3) * (VV + 1) + v] = l3;
                if (row0 + r0 + 0 < BTOT) out[((size_t)(row0 + r0 + 0) * TS + t) * VV + v] = l0;
                if (row0 + r0 + 1 < BTOT) out[((size_t)(row0 + r0 + 1) * TS + t) * VV + v] = l1;
                if (row0 + r0 + 2 < BTOT) out[((size_t)(row0 + r0 + 2) * TS + t) * VV + v] = l2;
                if (row0 + r0 + 3 < BTOT) out[((size_t)(row0 + r0 + 3) * TS + t) * VV + v] = l3;
            }
        }
        __syncthreads();                                        // B5
        // per-row argmax (first-max tie rule)
        if (tid < ROWS) {
            float m = lbuf[tid * (VV + 1)];
            int am = 0;
#pragma unroll 8
            for (int vv = 1; vv < VV; vv++) {
                float val = lbuf[tid * (VV + 1) + vv];
                if (val > m) { m = val; am = vv; }
            }
            s->tok[tid] = am;
        }
        __syncthreads();                                        // B6
    }
}

extern "C" void kernel_launch(void* const* d_in, const int* in_sizes, int n_in,
                              void* d_out, int out_size)
{
    const float* z     = (const float*)d_in[0];
    const float* emb   = (const float*)d_in[1];
    const float* z2h_w = (const float*)d_in[2];
    const float* z2h_b = (const float*)d_in[3];
    const float* out_w = (const float*)d_in[4];
    const float* out_b = (const float*)d_in[5];
    const float* wi0 = (const float*)d_in[6];
    const float* wh0 = (const float*)d_in[7];
    const float* bi0 = (const float*)d_in[8];
    const float* bh0 = (const float*)d_in[9];
    const float* wi1 = (const float*)d_in[10];
    const float* wh1 = (const float*)d_in[11];
    const float* bi1 = (const float*)d_in[12];
    const float* bh1 = (const float*)d_in[13];
    const float* wi2 = (const float*)d_in[14];
    const float* wh2 = (const float*)d_in[15];
    const float* bi2 = (const float*)d_in[16];
    const float* bh2 = (const float*)d_in[17];
    float* out = (float*)d_out;

    prep_kernel<<<1536, 256>>>(wi0, wh0, wi1, wh1, wi2, wh2, z2h_w, out_w);

    cudaFuncSetAttribute(moldec_kernel, cudaFuncAttributeMaxDynamicSharedMemorySize,
                         (int)sizeof(SM));
    moldec_kernel<<<NCTAS, NT, sizeof(SM)>>>(
        z, emb, z2h_b, out_b,
        bi0, bh0, bi1, bh1, bi2, bh2,
        out);
}

// round 15
// speedup vs baseline: 1.1515x; 1.1515x over previous
#include <cuda_runtime.h>
#include <cuda_bf16.h>

typedef unsigned long long ull;

#define NCTAS 147
#define NT    512
#define ROWS  28          // rows per CTA (last CTA partially valid)
#define HPAIR 7           // row pairs per thread (half of 14 rows)
#define RS    32          // padded row stride (floats); halves 16B-aligned
#define HH    256
#define EE    64
#define VV    64
#define ZZ    128
#define TS    119
#define BTOT  4096

// Compact weight layouts (built by prep): 12B per (k,j)  [round-13 proven]
// g_wrz2[k][j] = (w_r, w_z) ; g_wn1[k][j] = w_n
// k-slot bases: L0 wi:0(K=64) wh:64 | L1 wi:320 wh:576 | L2 wi:832 wh:1088
__device__ float2 g_wrz2[1344 * 256];
__device__ float  g_wn1 [1344 * 256];
__device__ float4 g_z3  [128 * 256];      // z2h: (row j, 256+j, 512+j, 0)
__device__ float2 g_ow  [256 * 64];       // out_w transposed + duplicated: [k][v]

struct SM {
    float hb[2][3][HH][RS];     // hidden state, double-buffered   196,608 B
    float xz[ZZ][RS];           // z/embedding; lbuf aliases this   16,384 B
    float br[3][HH];            // b_ih_r + b_hh_r
    float bz[3][HH];            // b_ih_z + b_hh_z
    float bin_[3][HH];          // b_ih_n
    float bhn_[3][HH];          // b_hh_n                           12,288 B
    int   tok[ROWS];            //                                     112 B
};                              // total ~225,392 B < 227 KB limit

__device__ __forceinline__ int slotof(int r) { return r + (r >= 14 ? 2 : 0); }

// ---------------- packed f32x2 helpers ----------------
__device__ __forceinline__ ull dup2(float v) {
    ull r; asm("mov.b64 %0, {%1, %1};" : "=l"(r) : "f"(v)); return r;
}
__device__ __forceinline__ void fma2(ull& d, ull a, ull b) {
    asm("fma.rn.f32x2 %0, %1, %2, %0;" : "+l"(d) : "l"(a), "l"(b));
}
__device__ __forceinline__ float f2lo(ull v) { return __uint_as_float((unsigned)(v & 0xffffffffULL)); }
__device__ __forceinline__ float f2hi(ull v) { return __uint_as_float((unsigned)(v >> 32)); }

// ---------------- flag-proof ~1ulp activations ----------------
__device__ __forceinline__ float exp_acc(float x) {
    x = fminf(fmaxf(x, -87.0f), 87.0f);
    float n = rintf(x * 1.4426950408889634f);
    float r = fmaf(n, -6.93145752e-01f, x);
    r = fmaf(n, -1.42860677e-06f, r);
    float p = 1.98412698412e-4f;
    p = fmaf(p, r, 1.38888888889e-3f);
    p = fmaf(p, r, 8.33333333333e-3f);
    p = fmaf(p, r, 4.16666666667e-2f);
    p = fmaf(p, r, 1.66666666667e-1f);
    p = fmaf(p, r, 0.5f);
    p = fmaf(p, r, 1.0f);
    p = fmaf(p, r, 1.0f);
    float sc = __int_as_float(((int)n + 127) << 23);
    return p * sc;
}
__device__ __forceinline__ float sigm(float x) {
    float e = exp_acc(-x);
    return __fdiv_rn(1.0f, 1.0f + e);
}
__device__ __forceinline__ float mytanh(float x) {
    float a = fabsf(x);
    float e = exp_acc(-2.0f * a);
    float r = __fdiv_rn(1.0f - e, 1.0f + e);
    return copysignf(r, x);
}

// ---------------- prep kernel ----------------
__global__ void prep_kernel(
    const float* __restrict__ wi0, const float* __restrict__ wh0,
    const float* __restrict__ wi1, const float* __restrict__ wh1,
    const float* __restrict__ wi2, const float* __restrict__ wh2,
    const float* __restrict__ z2h_w, const float* __restrict__ out_w)
{
    int bx = blockIdx.x;
    int j = threadIdx.x;
    if (bx < 1344) {
        const float* W; int ld, kk;
        if      (bx <   64) { W = wi0; ld =  64; kk = bx;        }
        else if (bx <  320) { W = wh0; ld = 256; kk = bx -   64; }
        else if (bx <  576) { W = wi1; ld = 256; kk = bx -  320; }
        else if (bx <  832) { W = wh1; ld = 256; kk = bx -  576; }
        else if (bx < 1088) { W = wi2; ld = 256; kk = bx -  832; }
        else                { W = wh2; ld = 256; kk = bx - 1088; }
        float wr = W[(size_t)j * ld + kk];
        float wz = W[(size_t)(256 + j) * ld + kk];
        float wn = W[(size_t)(512 + j) * ld + kk];
        g_wrz2[bx * 256 + j] = make_float2(wr, wz);
        g_wn1 [bx * 256 + j] = wn;
    } else if (bx < 1472) {
        int kz = bx - 1344;
        float4 v;
        v.x = z2h_w[(size_t)j * ZZ + kz];
        v.y = z2h_w[(size_t)(256 + j) * ZZ + kz];
        v.z = z2h_w[(size_t)(512 + j) * ZZ + kz];
        v.w = 0.0f;
        g_z3[kz * 256 + j] = v;
    } else {
        int m = bx - 1472;                 // 0..63
        int id = m * 256 + j;
        int k = id >> 6, v = id & 63;
        float w = out_w[(size_t)v * HH + k];
        g_ow[k * 64 + v] = make_float2(w, w);
    }
}

// ---------------- GEMM phase (round-13 proven): 3 gates, 7 row-pairs ----------------
// Direct-indexed compact loads, unroll 4 -> 8 LDGs in flight.
// acc sections: (0,1,SN) <- (r, z, n)
template<int K, int SN>
__device__ __forceinline__ void gemm3(const float2* __restrict__ wrz,
                                      const float* __restrict__ wn,
                                      const float* __restrict__ xb,
                                      ull (&acc)[4][HPAIR], int j)
{
    const float2* wp = wrz + j;
    const float*  np = wn  + j;
#pragma unroll 4
    for (int k = 0; k < K; k++) {
        float2 wc = __ldg(wp + (size_t)k * 256);
        float  nv = __ldg(np + (size_t)k * 256);
        ull wr = dup2(wc.x), wz = dup2(wc.y), wnn = dup2(nv);
        const ulonglong2* xq = (const ulonglong2*)(xb + (size_t)k * RS);
        ulonglong2 x0 = xq[0], x1 = xq[1], x2 = xq[2];
        ull x6 = ((const ull*)(xq + 3))[0];
        fma2(acc[0][0], wr, x0.x); fma2(acc[0][1], wr, x0.y);
        fma2(acc[0][2], wr, x1.x); fma2(acc[0][3], wr, x1.y);
        fma2(acc[0][4], wr, x2.x); fma2(acc[0][5], wr, x2.y);
        fma2(acc[0][6], wr, x6);
        fma2(acc[1][0], wz, x0.x); fma2(acc[1][1], wz, x0.y);
        fma2(acc[1][2], wz, x1.x); fma2(acc[1][3], wz, x1.y);
        fma2(acc[1][4], wz, x2.x); fma2(acc[1][5], wz, x2.y);
        fma2(acc[1][6], wz, x6);
        fma2(acc[SN][0], wnn, x0.x); fma2(acc[SN][1], wnn, x0.y);
        fma2(acc[SN][2], wnn, x1.x); fma2(acc[SN][3], wnn, x1.y);
        fma2(acc[SN][4], wnn, x2.x); fma2(acc[SN][5], wnn, x2.y);
        fma2(acc[SN][6], wnn, x6);
    }
}

// One GRU layer step (double-buffered: read cb, write nb; NO internal barriers).
template<int KIN>
__device__ __forceinline__ void layer_step(SM* s, const float* __restrict__ xb,
                                           const float2* __restrict__ wrzI,
                                           const float* __restrict__ wnI,
                                           const float2* __restrict__ wrzH,
                                           const float* __restrict__ wnH,
                                           const float* __restrict__ hcur,      // &hb[cb][l][0][ro]
                                           const float* __restrict__ hcur_row,  // &hb[cb][l][j][ro]
                                           float* __restrict__ hnxt_row,        // &hb[nb][l][j][ro]
                                           int l, int j)
{
    ull acc[4][HPAIR];
    {
        ull b0 = dup2(s->br[l][j]);
        ull b1 = dup2(s->bz[l][j]);
        ull b2 = dup2(s->bin_[l][j]);
        ull b3 = dup2(s->bhn_[l][j]);
#pragma unroll
        for (int p = 0; p < HPAIR; p++) {
            acc[0][p] = b0; acc[1][p] = b1; acc[2][p] = b2; acc[3][p] = b3;
        }
    }
    gemm3<KIN, 2>(wrzI, wnI, xb,   acc, j);   // x @ wi^T -> r, z, inn
    gemm3<HH,  3>(wrzH, wnH, hcur, acc, j);   // h @ wh^T -> r, z, hn
    // no barrier: writes go to the other buffer
#pragma unroll
    for (int p = 0; p < HPAIR; p++) {
        float2 hold = *(const float2*)(hcur_row + 2 * p);
        float rlo = sigm(f2lo(acc[0][p])), rhi = sigm(f2hi(acc[0][p]));
        float ulo = sigm(f2lo(acc[1][p])), uhi = sigm(f2hi(acc[1][p]));
        float nlo = mytanh(f2lo(acc[2][p]) + rlo * f2lo(acc[3][p]));
        float nhi = mytanh(f2hi(acc[2][p]) + rhi * f2hi(acc[3][p]));
        float2 hnew;
        hnew.x = (1.0f - ulo) * nlo + ulo * hold.x;
        hnew.y = (1.0f - uhi) * nhi + uhi * hold.y;
        *(float2*)(hnxt_row + 2 * p) = hnew;
    }
}

__global__ void __launch_bounds__(NT, 1) moldec_kernel(
    const float* __restrict__ z,     const float* __restrict__ emb,
    const float* __restrict__ z2h_b, const float* __restrict__ out_b,
    const float* __restrict__ bi0, const float* __restrict__ bh0,
    const float* __restrict__ bi1, const float* __restrict__ bh1,
    const float* __restrict__ bi2, const float* __restrict__ bh2,
    float* __restrict__ out)
{
    extern __shared__ char smraw[];
    SM* s = (SM*)smraw;
    const int tid = threadIdx.x;
    const int row0 = blockIdx.x * ROWS;
    const int j  = tid & 255;      // gate index
    const int rh = tid >> 8;       // row half
    const int ro = rh * 16;        // slot offset of this half
    float* lbuf = &s->xz[0][0];    // aliases xz (time-disjoint; stride VV+1)

    // combined biases to smem
    {
        const float* bip[3] = {bi0, bi1, bi2};
        const float* bhp[3] = {bh0, bh1, bh2};
        for (int i = tid; i < 3 * HH; i += NT) {
            int l = i >> 8, jj = i & 255;
            s->br[l][jj]   = bip[l][jj]          + bhp[l][jj];
            s->bz[l][jj]   = bip[l][HH + jj]     + bhp[l][HH + jj];
            s->bin_[l][jj] = bip[l][2 * HH + jj];
            s->bhn_[l][jj] = bhp[l][2 * HH + jj];
        }
    }
    // stage z transposed (k-major, slot-mapped), zero-fill invalid rows
    for (int i = tid; i < ZZ * ROWS; i += NT) {
        int r = i >> 7, k = i & 127;
        int grow = row0 + r;
        s->xz[k][slotof(r)] = (grow < BTOT) ? z[(size_t)grow * ZZ + k] : 0.0f;
    }
    // zero pad slots (14,15,30,31) of every k-row in BOTH hb buffers + xz
    for (int i = tid; i < 2 * 3 * HH + ZZ; i += NT) {
        float* rowp;
        if (i < 2 * 3 * HH) {
            int b = i / (3 * HH), rem = i - b * 3 * HH;
            rowp = &s->hb[b][rem >> 8][rem & 255][0];
        } else {
            rowp = &s->xz[i - 2 * 3 * HH][0];
        }
        rowp[14] = 0.0f; rowp[15] = 0.0f; rowp[30] = 0.0f; rowp[31] = 0.0f;
    }
    if (tid < ROWS) s->tok[tid] = 1;
    __syncthreads();

    // initial hidden into buffer 0: h0[l] = tanh(z @ z2h_w^T + z2h_b)
    {
        ull acc[4][HPAIR];
#pragma unroll
        for (int ss = 0; ss < 3; ss++) {
            ull b = dup2(z2h_b[ss * 256 + j]);
#pragma unroll
            for (int p = 0; p < HPAIR; p++) acc[ss][p] = b;
        }
#pragma unroll
        for (int p = 0; p < HPAIR; p++) acc[3][p] = 0ULL;
        const float4* zp = g_z3 + j;
#pragma unroll 2
        for (int k = 0; k < ZZ; k++) {
            float4 wc = __ldg(zp + (size_t)k * 256);
            ull wa = dup2(wc.x), wb = dup2(wc.y), wcn = dup2(wc.z);
            const ull* xq = (const ull*)(&s->xz[k][ro]);
#pragma unroll
            for (int p = 0; p < HPAIR; p++) {
                ull xv = xq[p];
                fma2(acc[0][p], wa, xv);
                fma2(acc[1][p], wb, xv);
                fma2(acc[2][p], wcn, xv);
            }
        }
#pragma unroll
        for (int ss = 0; ss < 3; ss++) {
            float* hrow = &s->hb[0][ss][j][ro];
#pragma unroll
            for (int p = 0; p < HPAIR; p++) {
                float2 hv;
                hv.x = mytanh(f2lo(acc[ss][p]));
                hv.y = mytanh(f2hi(acc[ss][p]));
                *(float2*)(hrow + 2 * p) = hv;
            }
        }
        __syncthreads();
    }

    const float2* wrzi0 = g_wrz2;              const float* wni0 = g_wn1;
    const float2* wrzh0 = g_wrz2 +   64 * 256; const float* wnh0 = g_wn1 +   64 * 256;
    const float2* wrzi1 = g_wrz2 +  320 * 256; const float* wni1 = g_wn1 +  320 * 256;
    const float2* wrzh1 = g_wrz2 +  576 * 256; const float* wnh1 = g_wn1 +  576 * 256;
    const float2* wrzi2 = g_wrz2 +  832 * 256; const float* wni2 = g_wn1 +  832 * 256;
    const float2* wrzh2 = g_wrz2 + 1088 * 256; const float* wnh2 = g_wn1 + 1088 * 256;

    // out-proj thread mapping
    const int v = tid & 63;
    const int g = tid >> 6;            // 0..7
    const int gval = (g < 7);
    const int so0 = gval ? slotof(g * 4)     : 0;
    const int so1 = gval ? slotof(g * 4 + 2) : 0;
    const float ob = out_b[v];

    // decode loop
    for (int t = 0; t < TS; t++) {
        const int cb = t & 1, nb = cb ^ 1;

        // embedding gather into xz (k-major, slot-mapped)
        for (int i = tid; i < EE * ROWS; i += NT) {
            int r = i >> 6, k = i & 63;
            s->xz[k][slotof(r)] = emb[(size_t)s->tok[r] * EE + k];
        }
        __syncthreads();                                        // B1

        layer_step<EE>(s, &s->xz[0][ro], wrzi0, wni0, wrzh0, wnh0,
                       &s->hb[cb][0][0][ro], &s->hb[cb][0][j][ro], &s->hb[nb][0][j][ro], 0, j);
        __syncthreads();                                        // B2
        layer_step<HH>(s, &s->hb[nb][0][0][ro], wrzi1, wni1, wrzh1, wnh1,
                       &s->hb[cb][1][0][ro], &s->hb[cb][1][j][ro], &s->hb[nb][1][j][ro], 1, j);
        __syncthreads();                                        // B3
        layer_step<HH>(s, &s->hb[nb][1][0][ro], wrzi2, wni2, wrzh2, wnh2,
                       &s->hb[cb][2][0][ro], &s->hb[cb][2][j][ro], &s->hb[nb][2][j][ro], 2, j);
        __syncthreads();                                        // B4

        // output projection: logits = hb[nb][2] @ out_w^T + out_b
        {
            ull o0 = dup2(ob);
            ull o1 = o0;
            const float* xs = &s->hb[nb][2][0][0];
            const ull* owp = (const ull*)g_ow;
            for (int kb = 0; kb < HH; kb += 8) {
                ull wreg[8];
#pragma unroll
                for (int i = 0; i < 8; i++) wreg[i] = owp[(kb + i) * 64 + v];
#pragma unroll
                for (int i = 0; i < 8; i++) {
                    const float* xrow = xs + (size_t)(kb + i) * RS;
                    fma2(o0, wreg[i], *(const ull*)(xrow + so0));
                    fma2(o1, wreg[i], *(const ull*)(xrow + so1));
                }
            }
            if (gval) {
                int r0 = g * 4;
                float l0 = f2lo(o0), l1 = f2hi(o0), l2 = f2lo(o1), l3 = f2hi(o1);
                lbuf[(r0 + 0) * (VV + 1) + v] = l0;
                lbuf[(r0 + 1) * (VV + 1) + v] = l1;
                lbuf[(r0 + 2) * (VV + 1) + v] = l2;
                lbuf[(r0 + 3) * (VV + 1) + v] = l3;
                if (row0 + r0 + 0 < BTOT) out[((size_t)(row0 + r0 + 0) * TS + t) * VV + v] = l0;
                if (row0 + r0 + 1 < BTOT) out[((size_t)(row0 + r0 + 1) * TS + t) * VV + v] = l1;
                if (row0 + r0 + 2 < BTOT) out[((size_t)(row0 + r0 + 2) * TS + t) * VV + v] = l2;
                if (row0 + r0 + 3 < BTOT) out[((size_t)(row0 + r0 + 3) * TS + t) * VV + v] = l3;
            }
        }
        __syncthreads();                                        // B5
        // per-row argmax (first-max tie rule)
        if (tid < ROWS) {
            float m = lbuf[tid * (VV + 1)];
            int am = 0;
#pragma unroll 8
            for (int vv = 1; vv < VV; vv++) {
                float val = lbuf[tid * (VV + 1) + vv];
                if (val > m) { m = val; am = vv; }
            }
            s->tok[tid] = am;
        }
        __syncthreads();                                        // B6
    }
}

extern "C" void kernel_launch(void* const* d_in, const int* in_sizes, int n_in,
                              void* d_out, int out_size)
{
    const float* z     = (const float*)d_in[0];
    const float* emb   = (const float*)d_in[1];
    const float* z2h_w = (const float*)d_in[2];
    const float* z2h_b = (const float*)d_in[3];
    const float* out_w = (const float*)d_in[4];
    const float* out_b = (const float*)d_in[5];
    const float* wi0 = (const float*)d_in[6];
    const float* wh0 = (const float*)d_in[7];
    const float* bi0 = (const float*)d_in[8];
    const float* bh0 = (const float*)d_in[9];
    const float* wi1 = (const float*)d_in[10];
    const float* wh1 = (const float*)d_in[11];
    const float* bi1 = (const float*)d_in[12];
    const float* bh1 = (const float*)d_in[13];
    const float* wi2 = (const float*)d_in[14];
    const float* wh2 = (const float*)d_in[15];
    const float* bi2 = (const float*)d_in[16];
    const float* bh2 = (const float*)d_in[17];
    float* out = (float*)d_out;

    prep_kernel<<<1536, 256>>>(wi0, wh0, wi1, wh1, wi2, wh2, z2h_w, out_w);

    cudaFuncSetAttribute(moldec_kernel, cudaFuncAttributeMaxDynamicSharedMemorySize,
                         (int)sizeof(SM));
    moldec_kernel<<<NCTAS, NT, sizeof(SM)>>>(
        z, emb, z2h_b, out_b,
        bi0, bh0, bi1, bh1, bi2, bh2,
        out);
}

// round 16
// speedup vs baseline: 1.1520x; 1.0005x over previous
#include <cuda_runtime.h>
#include <cuda_bf16.h>

typedef unsigned long long ull;

#define NCTAS 147
#define NT    512
#define ROWS  28          // rows per CTA (last CTA partially valid)
#define HPAIR 7           // row pairs per thread (half of 14 rows)
#define RS    32          // padded row stride (floats); halves 16B-aligned
#define HH    256
#define EE    64
#define VV    64
#define ZZ    128
#define TS    119
#define BTOT  4096

// Compact weight layouts (built by prep): 12B per (k,j)  [round-13 proven]
// g_wrz2[k][j] = (w_r, w_z) ; g_wn1[k][j] = w_n
// k-slot bases: L0 wi:0(K=64) wh:64 | L1 wi:320 wh:576 | L2 wi:832 wh:1088
__device__ float2 g_wrz2[1344 * 256];
__device__ float  g_wn1 [1344 * 256];
__device__ float4 g_z3  [128 * 256];      // z2h: (row j, 256+j, 512+j, 0)
__device__ float2 g_ow  [256 * 64];       // out_w transposed + duplicated: [k][v]

struct SM {
    float hb[2][3][HH][RS];     // hidden state, double-buffered   196,608 B
    float xz[ZZ][RS];           // z/embedding; lbuf aliases this   16,384 B
    float br[3][HH];            // b_ih_r + b_hh_r
    float bz[3][HH];            // b_ih_z + b_hh_z
    float bin_[3][HH];          // b_ih_n
    float bhn_[3][HH];          // b_hh_n                           12,288 B
    int   tok[ROWS];            //                                     112 B
};                              // total ~225,392 B < 227 KB limit

__device__ __forceinline__ int slotof(int r) { return r + (r >= 14 ? 2 : 0); }

// ---------------- packed f32x2 helpers ----------------
__device__ __forceinline__ ull dup2(float v) {
    ull r; asm("mov.b64 %0, {%1, %1};" : "=l"(r) : "f"(v)); return r;
}
__device__ __forceinline__ void fma2(ull& d, ull a, ull b) {
    asm("fma.rn.f32x2 %0, %1, %2, %0;" : "+l"(d) : "l"(a), "l"(b));
}
__device__ __forceinline__ float f2lo(ull v) { return __uint_as_float((unsigned)(v & 0xffffffffULL)); }
__device__ __forceinline__ float f2hi(ull v) { return __uint_as_float((unsigned)(v >> 32)); }

// ---------------- flag-proof ~1ulp activations ----------------
__device__ __forceinline__ float exp_acc(float x) {
    x = fminf(fmaxf(x, -87.0f), 87.0f);
    float n = rintf(x * 1.4426950408889634f);
    float r = fmaf(n, -6.93145752e-01f, x);
    r = fmaf(n, -1.42860677e-06f, r);
    float p = 1.98412698412e-4f;
    p = fmaf(p, r, 1.38888888889e-3f);
    p = fmaf(p, r, 8.33333333333e-3f);
    p = fmaf(p, r, 4.16666666667e-2f);
    p = fmaf(p, r, 1.66666666667e-1f);
    p = fmaf(p, r, 0.5f);
    p = fmaf(p, r, 1.0f);
    p = fmaf(p, r, 1.0f);
    float sc = __int_as_float(((int)n + 127) << 23);
    return p * sc;
}
__device__ __forceinline__ float sigm(float x) {
    float e = exp_acc(-x);
    return __fdiv_rn(1.0f, 1.0f + e);
}
__device__ __forceinline__ float mytanh(float x) {
    float a = fabsf(x);
    float e = exp_acc(-2.0f * a);
    float r = __fdiv_rn(1.0f - e, 1.0f + e);
    return copysignf(r, x);
}

// ---------------- prep kernel ----------------
__global__ void prep_kernel(
    const float* __restrict__ wi0, const float* __restrict__ wh0,
    const float* __restrict__ wi1, const float* __restrict__ wh1,
    const float* __restrict__ wi2, const float* __restrict__ wh2,
    const float* __restrict__ z2h_w, const float* __restrict__ out_w)
{
    int bx = blockIdx.x;
    int j = threadIdx.x;
    if (bx < 1344) {
        const float* W; int ld, kk;
        if      (bx <   64) { W = wi0; ld =  64; kk = bx;        }
        else if (bx <  320) { W = wh0; ld = 256; kk = bx -   64; }
        else if (bx <  576) { W = wi1; ld = 256; kk = bx -  320; }
        else if (bx <  832) { W = wh1; ld = 256; kk = bx -  576; }
        else if (bx < 1088) { W = wi2; ld = 256; kk = bx -  832; }
        else                { W = wh2; ld = 256; kk = bx - 1088; }
        float wr = W[(size_t)j * ld + kk];
        float wz = W[(size_t)(256 + j) * ld + kk];
        float wn = W[(size_t)(512 + j) * ld + kk];
        g_wrz2[bx * 256 + j] = make_float2(wr, wz);
        g_wn1 [bx * 256 + j] = wn;
    } else if (bx < 1472) {
        int kz = bx - 1344;
        float4 v;
        v.x = z2h_w[(size_t)j * ZZ + kz];
        v.y = z2h_w[(size_t)(256 + j) * ZZ + kz];
        v.z = z2h_w[(size_t)(512 + j) * ZZ + kz];
        v.w = 0.0f;
        g_z3[kz * 256 + j] = v;
    } else {
        int m = bx - 1472;                 // 0..63
        int id = m * 256 + j;
        int k = id >> 6, v = id & 63;
        float w = out_w[(size_t)v * HH + k];
        g_ow[k * 64 + v] = make_float2(w, w);
    }
}

// ---------------- GEMM phase (round-13 proven): 3 gates, 7 row-pairs ----------------
// Direct-indexed compact loads, unroll 4 -> 8 LDGs in flight.
// acc sections: (0,1,SN) <- (r, z, n)
template<int K, int SN>
__device__ __forceinline__ void gemm3(const float2* __restrict__ wrz,
                                      const float* __restrict__ wn,
                                      const float* __restrict__ xb,
                                      ull (&acc)[4][HPAIR], int j)
{
    const float2* wp = wrz + j;
    const float*  np = wn  + j;
#pragma unroll 4
    for (int k = 0; k < K; k++) {
        float2 wc = __ldg(wp + (size_t)k * 256);
        float  nv = __ldg(np + (size_t)k * 256);
        ull wr = dup2(wc.x), wz = dup2(wc.y), wnn = dup2(nv);
        const ulonglong2* xq = (const ulonglong2*)(xb + (size_t)k * RS);
        ulonglong2 x0 = xq[0], x1 = xq[1], x2 = xq[2];
        ull x6 = ((const ull*)(xq + 3))[0];
        fma2(acc[0][0], wr, x0.x); fma2(acc[0][1], wr, x0.y);
        fma2(acc[0][2], wr, x1.x); fma2(acc[0][3], wr, x1.y);
        fma2(acc[0][4], wr, x2.x); fma2(acc[0][5], wr, x2.y);
        fma2(acc[0][6], wr, x6);
        fma2(acc[1][0], wz, x0.x); fma2(acc[1][1], wz, x0.y);
        fma2(acc[1][2], wz, x1.x); fma2(acc[1][3], wz, x1.y);
        fma2(acc[1][4], wz, x2.x); fma2(acc[1][5], wz, x2.y);
        fma2(acc[1][6], wz, x6);
        fma2(acc[SN][0], wnn, x0.x); fma2(acc[SN][1], wnn, x0.y);
        fma2(acc[SN][2], wnn, x1.x); fma2(acc[SN][3], wnn, x1.y);
        fma2(acc[SN][4], wnn, x2.x); fma2(acc[SN][5], wnn, x2.y);
        fma2(acc[SN][6], wnn, x6);
    }
}

// One GRU layer step (double-buffered: read cb, write nb; NO internal barriers).
template<int KIN>
__device__ __forceinline__ void layer_step(SM* s, const float* __restrict__ xb,
                                           const float2* __restrict__ wrzI,
                                           const float* __restrict__ wnI,
                                           const float2* __restrict__ wrzH,
                                           const float* __restrict__ wnH,
                                           const float* __restrict__ hcur,      // &hb[cb][l][0][ro]
                                           const float* __restrict__ hcur_row,  // &hb[cb][l][j][ro]
                                           float* __restrict__ hnxt_row,        // &hb[nb][l][j][ro]
                                           int l, int j)
{
    ull acc[4][HPAIR];
    {
        ull b0 = dup2(s->br[l][j]);
        ull b1 = dup2(s->bz[l][j]);
        ull b2 = dup2(s->bin_[l][j]);
        ull b3 = dup2(s->bhn_[l][j]);
#pragma unroll
        for (int p = 0; p < HPAIR; p++) {
            acc[0][p] = b0; acc[1][p] = b1; acc[2][p] = b2; acc[3][p] = b3;
        }
    }
    gemm3<KIN, 2>(wrzI, wnI, xb,   acc, j);   // x @ wi^T -> r, z, inn
    gemm3<HH,  3>(wrzH, wnH, hcur, acc, j);   // h @ wh^T -> r, z, hn
    // no barrier: writes go to the other buffer
#pragma unroll
    for (int p = 0; p < HPAIR; p++) {
        float2 hold = *(const float2*)(hcur_row + 2 * p);
        float rlo = sigm(f2lo(acc[0][p])), rhi = sigm(f2hi(acc[0][p]));
        float ulo = sigm(f2lo(acc[1][p])), uhi = sigm(f2hi(acc[1][p]));
        float nlo = mytanh(f2lo(acc[2][p]) + rlo * f2lo(acc[3][p]));
        float nhi = mytanh(f2hi(acc[2][p]) + rhi * f2hi(acc[3][p]));
        float2 hnew;
        hnew.x = (1.0f - ulo) * nlo + ulo * hold.x;
        hnew.y = (1.0f - uhi) * nhi + uhi * hold.y;
        *(float2*)(hnxt_row + 2 * p) = hnew;
    }
}

__global__ void __launch_bounds__(NT, 1) moldec_kernel(
    const float* __restrict__ z,     const float* __restrict__ emb,
    const float* __restrict__ z2h_b, const float* __restrict__ out_b,
    const float* __restrict__ bi0, const float* __restrict__ bh0,
    const float* __restrict__ bi1, const float* __restrict__ bh1,
    const float* __restrict__ bi2, const float* __restrict__ bh2,
    float* __restrict__ out)
{
    extern __shared__ char smraw[];
    SM* s = (SM*)smraw;
    const int tid = threadIdx.x;
    const int row0 = blockIdx.x * ROWS;
    const int j  = tid & 255;      // gate index
    const int rh = tid >> 8;       // row half
    const int ro = rh * 16;        // slot offset of this half
    float* lbuf = &s->xz[0][0];    // aliases xz (time-disjoint; stride VV+1)

    // combined biases to smem
    {
        const float* bip[3] = {bi0, bi1, bi2};
        const float* bhp[3] = {bh0, bh1, bh2};
        for (int i = tid; i < 3 * HH; i += NT) {
            int l = i >> 8, jj = i & 255;
            s->br[l][jj]   = bip[l][jj]          + bhp[l][jj];
            s->bz[l][jj]   = bip[l][HH + jj]     + bhp[l][HH + jj];
            s->bin_[l][jj] = bip[l][2 * HH + jj];
            s->bhn_[l][jj] = bhp[l][2 * HH + jj];
        }
    }
    // stage z transposed (k-major, slot-mapped), zero-fill invalid rows
    for (int i = tid; i < ZZ * ROWS; i += NT) {
        int r = i >> 7, k = i & 127;
        int grow = row0 + r;
        s->xz[k][slotof(r)] = (grow < BTOT) ? z[(size_t)grow * ZZ + k] : 0.0f;
    }
    // zero pad slots (14,15,30,31) of every k-row in BOTH hb buffers + xz
    for (int i = tid; i < 2 * 3 * HH + ZZ; i += NT) {
        float* rowp;
        if (i < 2 * 3 * HH) {
            int b = i / (3 * HH), rem = i - b * 3 * HH;
            rowp = &s->hb[b][rem >> 8][rem & 255][0];
        } else {
            rowp = &s->xz[i - 2 * 3 * HH][0];
        }
        rowp[14] = 0.0f; rowp[15] = 0.0f; rowp[30] = 0.0f; rowp[31] = 0.0f;
    }
    if (tid < ROWS) s->tok[tid] = 1;
    __syncthreads();

    // initial hidden into buffer 0: h0[l] = tanh(z @ z2h_w^T + z2h_b)
    {
        ull acc[4][HPAIR];
#pragma unroll
        for (int ss = 0; ss < 3; ss++) {
            ull b = dup2(z2h_b[ss * 256 + j]);
#pragma unroll
            for (int p = 0; p < HPAIR; p++) acc[ss][p] = b;
        }
#pragma unroll
        for (int p = 0; p < HPAIR; p++) acc[3][p] = 0ULL;
        const float4* zp = g_z3 + j;
#pragma unroll 2
        for (int k = 0; k < ZZ; k++) {
            float4 wc = __ldg(zp + (size_t)k * 256);
            ull wa = dup2(wc.x), wb = dup2(wc.y), wcn = dup2(wc.z);
            const ull* xq = (const ull*)(&s->xz[k][ro]);
#pragma unroll
            for (int p = 0; p < HPAIR; p++) {
                ull xv = xq[p];
                fma2(acc[0][p], wa, xv);
                fma2(acc[1][p], wb, xv);
                fma2(acc[2][p], wcn, xv);
            }
        }
#pragma unroll
        for (int ss = 0; ss < 3; ss++) {
            float* hrow = &s->hb[0][ss][j][ro];
#pragma unroll
            for (int p = 0; p < HPAIR; p++) {
                float2 hv;
                hv.x = mytanh(f2lo(acc[ss][p]));
                hv.y = mytanh(f2hi(acc[ss][p]));
                *(float2*)(hrow + 2 * p) = hv;
            }
        }
        __syncthreads();
    }

    const float2* wrzi0 = g_wrz2;              const float* wni0 = g_wn1;
    const float2* wrzh0 = g_wrz2 +   64 * 256; const float* wnh0 = g_wn1 +   64 * 256;
    const float2* wrzi1 = g_wrz2 +  320 * 256; const float* wni1 = g_wn1 +  320 * 256;
    const float2* wrzh1 = g_wrz2 +  576 * 256; const float* wnh1 = g_wn1 +  576 * 256;
    const float2* wrzi2 = g_wrz2 +  832 * 256; const float* wni2 = g_wn1 +  832 * 256;
    const float2* wrzh2 = g_wrz2 + 1088 * 256; const float* wnh2 = g_wn1 + 1088 * 256;

    // out-proj thread mapping
    const int v = tid & 63;
    const int g = tid >> 6;            // 0..7
    const int gval = (g < 7);
    const int so0 = gval ? slotof(g * 4)     : 0;
    const int so1 = gval ? slotof(g * 4 + 2) : 0;
    const float ob = out_b[v];

    // decode loop
    for (int t = 0; t < TS; t++) {
        const int cb = t & 1, nb = cb ^ 1;

        // embedding gather into xz (k-major, slot-mapped)
        for (int i = tid; i < EE * ROWS; i += NT) {
            int r = i >> 6, k = i & 63;
            s->xz[k][slotof(r)] = emb[(size_t)s->tok[r] * EE + k];
        }
        __syncthreads();                                        // B1

        layer_step<EE>(s, &s->xz[0][ro], wrzi0, wni0, wrzh0, wnh0,
                       &s->hb[cb][0][0][ro], &s->hb[cb][0][j][ro], &s->hb[nb][0][j][ro], 0, j);
        __syncthreads();                                        // B2
        layer_step<HH>(s, &s->hb[nb][0][0][ro], wrzi1, wni1, wrzh1, wnh1,
                       &s->hb[cb][1][0][ro], &s->hb[cb][1][j][ro], &s->hb[nb][1][j][ro], 1, j);
        __syncthreads();                                        // B3
        layer_step<HH>(s, &s->hb[nb][1][0][ro], wrzi2, wni2, wrzh2, wnh2,
                       &s->hb[cb][2][0][ro], &s->hb[cb][2][j][ro], &s->hb[nb][2][j][ro], 2, j);
        __syncthreads();                                        // B4

        // output projection: logits = hb[nb][2] @ out_w^T + out_b
        {
            ull o0 = dup2(ob);
            ull o1 = o0;
            const float* xs = &s->hb[nb][2][0][0];
            const ull* owp = (const ull*)g_ow;
            for (int kb = 0; kb < HH; kb += 8) {
                ull wreg[8];
#pragma unroll
                for (int i = 0; i < 8; i++) wreg[i] = owp[(kb + i) * 64 + v];
#pragma unroll
                for (int i = 0; i < 8; i++) {
                    const float* xrow = xs + (size_t)(kb + i) * RS;
                    fma2(o0, wreg[i], *(const ull*)(xrow + so0));
                    fma2(o1, wreg[i], *(const ull*)(xrow + so1));
                }
            }
            if (gval) {
                int r0 = g * 4;
                float l0 = f2lo(o0), l1 = f2hi(o0), l2 = f2lo(o1), l3 = f2hi(o1);
                lbuf[(r0 + 0) * (VV + 1) + v] = l0;
                lbuf[(r0 + 1) * (VV + 1) + v] = l1;
                lbuf[(r0 + 2) * (VV + 1) + v] = l2;
                lbuf[(r0 + 3) * (VV + 1) + v] = l3;
                if (row0 + r0 + 0 < BTOT) out[((size_t)(row0 + r0 + 0) * TS + t) * VV + v] = l0;
                if (row0 + r0 + 1 < BTOT) out[((size_t)(row0 + r0 + 1) * TS + t) * VV + v] = l1;
                if (row0 + r0 + 2 < BTOT) out[((size_t)(row0 + r0 + 2) * TS + t) * VV + v] = l2;
                if (row0 + r0 + 3 < BTOT) out[((size_t)(row0 + r0 + 3) * TS + t) * VV + v] = l3;
            }
        }
        __syncthreads();                                        // B5
        // per-row argmax (first-max tie rule)
        if (tid < ROWS) {
            float m = lbuf[tid * (VV + 1)];
            int am = 0;
#pragma unroll 8
            for (int vv = 1; vv < VV; vv++) {
                float val = lbuf[tid * (VV + 1) + vv];
                if (val > m) { m = val; am = vv; }
            }
            s->tok[tid] = am;
        }
        __syncthreads();                                        // B6
    }
}

extern "C" void kernel_launch(void* const* d_in, const int* in_sizes, int n_in,
                              void* d_out, int out_size)
{
    const float* z     = (const float*)d_in[0];
    const float* emb   = (const float*)d_in[1];
    const float* z2h_w = (const float*)d_in[2];
    const float* z2h_b = (const float*)d_in[3];
    const float* out_w = (const float*)d_in[4];
    const float* out_b = (const float*)d_in[5];
    const float* wi0 = (const float*)d_in[6];
    const float* wh0 = (const float*)d_in[7];
    const float* bi0 = (const float*)d_in[8];
    const float* bh0 = (const float*)d_in[9];
    const float* wi1 = (const float*)d_in[10];
    const float* wh1 = (const float*)d_in[11];
    const float* bi1 = (const float*)d_in[12];
    const float* bh1 = (const float*)d_in[13];
    const float* wi2 = (const float*)d_in[14];
    const float* wh2 = (const float*)d_in[15];
    const float* bi2 = (const float*)d_in[16];
    const float* bh2 = (const float*)d_in[17];
    float* out = (float*)d_out;

    prep_kernel<<<1536, 256>>>(wi0, wh0, wi1, wh1, wi2, wh2, z2h_w, out_w);

    cudaFuncSetAttribute(moldec_kernel, cudaFuncAttributeMaxDynamicSharedMemorySize,
                         (int)sizeof(SM));
    moldec_kernel<<<NCTAS, NT, sizeof(SM)>>>(
        z, emb, z2h_b, out_b,
        bi0, bh0, bi1, bh1, bi2, bh2,
        out);
}